// round 11
// baseline (speedup 1.0000x reference)
#include <cuda_runtime.h>
#include <cuda_fp16.h>
#include <cstdint>
#include <math.h>

// Shapes (fixed):
//   x:[256,128,512], W_ih:[4096,512], W_hh:[4096,1024], b_ih/b_hh:[4096]
//   W1:[1024,1024], b1:[1024], W2:[128,1024], b2:[128]
//   d_out = (output[256,128], pre_output[256,1024])
#define NB   256
#define TT   128
#define DIN  512
#define HD   1024
#define ODIM 128
#define G4   4096
#define KC   128           // K halves per chunk (unified h|x K-space, 1536 total)
#define NCHUNK 12          // 1536 / 128
// Hybrid split per chunk: tensor warps take halves 0..111 (7 x k16),
// SIMT fp32 warps take halves 112..127 (8 k-pairs). 1344 + 192 = 1536.
#define TK16   7

// -------- scratch (__device__ globals; no allocation allowed) --------
__device__ __half g_h[2][NB * HD];             // ping-pong hidden state (fp16)
__device__ float  g_hf[NB * HD];               // final h in fp32 for head
__device__ float  g_c[NB * HD];                // cell state (fp32)
__device__ __half g_whh[(size_t)G4 * HD];      // RN-fp16 W_hh
__device__ __half g_wih[(size_t)G4 * DIN];     // RN-fp16 W_ih
__device__ __half g_x[(size_t)NB * TT * DIN];  // RN-fp16 x

// -------- smem: 3-stage circular fp16 tiles + bias + SIMT partial buf ----
#define ASTW 68                                 // tile row stride in words
#define A_BYTES (128 * ASTW * 4)
#define B_BYTES (64 * ASTW * 4)
#define OFF_AS(s) ((s) * A_BYTES)
#define OFF_BS(s) (3 * A_BYTES + (s) * B_BYTES)
#define OFF_BIAS  (3 * (A_BYTES + B_BYTES))
#define OFF_PART  (OFF_BIAS + 256)              // 128 x 64 f32, row stride 66
#define SMEM_DYN  (OFF_PART + 128 * 66 * 4)     // 190,720 B (< 227 KB)

__device__ __forceinline__ uint32_t smem_u32(const void* p) {
    uint32_t a;
    asm("{ .reg .u64 t; cvta.to.shared.u64 t, %1; cvt.u32.u64 %0, t; }"
        : "=r"(a) : "l"(p));
    return a;
}
__device__ __forceinline__ void cp16(uint32_t dst, const void* src) {
    asm volatile("cp.async.cg.shared.global [%0], [%1], 16;" :: "r"(dst), "l"(src) : "memory");
}
#define CP_COMMIT() asm volatile("cp.async.commit_group;" ::: "memory")

__device__ __forceinline__ void mma16(float* d, const uint32_t* a, const uint32_t* b) {
    asm volatile(
        "mma.sync.aligned.m16n8k16.row.col.f32.f16.f16.f32 "
        "{%0,%1,%2,%3}, {%4,%5,%6,%7}, {%8,%9}, {%0,%1,%2,%3};"
        : "+f"(d[0]), "+f"(d[1]), "+f"(d[2]), "+f"(d[3])
        : "r"(a[0]), "r"(a[1]), "r"(a[2]), "r"(a[3]), "r"(b[0]), "r"(b[1]));
}

__device__ __forceinline__ float sigm(float x) { return 1.0f / (1.0f + __expf(-x)); }
__device__ __forceinline__ float tanh_f(float x) {
    return fmaf(-2.0f, 1.0f / (__expf(2.0f * x) + 1.0f), 1.0f);
}

// ===================== recurrence step kernel (hybrid) =====================
// grid (64,2): bx -> 16 hidden units (j0), by -> M-tile of 128.
// Warps 0-7: fp16 MMA on chunk halves 0..111. Warps 8-11: SIMT fp32 FFMA on
// halves 112..127 (FMA pipe runs concurrently with tensor pipe).
// D[128,64] cols: n = warpN*32 + gate*8 + u. B tile row rr -> W row
// gate(rr)*HD + j0 + (rr>>5)*8 + (rr&7), gate = (rr>>3)&3.
__global__ __launch_bounds__(384, 1) void lstm_step_tc(
    const __half* __restrict__ h_in, __half* __restrict__ h_out,
    const __half* __restrict__ xr, const __half* __restrict__ whr,
    const __half* __restrict__ wir,
    const float* __restrict__ b_ih, const float* __restrict__ b_hh, int t)
{
    extern __shared__ char smc[];
    const uint32_t sb = smem_u32(smc);
    float* biasS = (float*)(smc + OFF_BIAS);
    float* part  = (float*)(smc + OFF_PART);
    const int tid  = threadIdx.x;
    const int wid  = tid >> 5;
    const int lane = tid & 31;
    const int j0    = blockIdx.x * 16;
    const int mBase = blockIdx.y * 128;
    const int warpM = wid >> 1, warpN = wid & 1;   // MMA warps only
    const int g_l = lane >> 2, t4 = lane & 3;

    if (tid < 64) {
        int phys = ((tid >> 3) & 3) * HD + j0 + (tid >> 5) * 8 + (tid & 7);
        biasS[tid] = b_ih[phys] + b_hh[phys];
    }

    auto load_chunk = [&](int c, int s) {        // executed by MMA warps only
        if (tid >= 256) return;
        const uint32_t ab   = sb + OFF_AS(s);
        const uint32_t bbuf = sb + OFF_BS(s);
#pragma unroll
        for (int i = 0; i < 8; i++) {            // A tile: 128 rows x 128 halves
            int u   = tid + i * 256;
            int r   = u >> 4;
            int kl8 = (u & 15) * 8;
            int kg  = c * KC + kl8;
            const __half* src = (kg < HD)
                ? h_in + (size_t)(mBase + r) * HD + kg
                : xr + ((size_t)(mBase + r) * TT + t) * DIN + (kg - HD);
            cp16(ab + (r * ASTW * 4 + kl8 * 2), src);
        }
#pragma unroll
        for (int i = 0; i < 4; i++) {            // B tile: 64 rows x 128 halves
            int u   = tid + i * 256;
            int rr  = u >> 4;
            int kl8 = (u & 15) * 8;
            int kg  = c * KC + kl8;
            int phys = ((rr >> 3) & 3) * HD + j0 + (rr >> 5) * 8 + (rr & 7);
            const __half* src = (kg < HD)
                ? whr + (size_t)phys * HD + kg
                : wir + (size_t)phys * DIN + (kg - HD);
            cp16(bbuf + (rr * ASTW * 4 + kl8 * 2), src);
        }
        CP_COMMIT();
    };

    // MMA accumulators (warps 0-7) / SIMT accumulators (warps 8-11)
    float acc[2][4][4];
    float sacc[8][8];
    const int sw = wid - 8;                      // SIMT warp index 0..3
    const int lr = lane >> 3, lc = lane & 7;     // SIMT lane tile coords
    if (wid < 8) {
#pragma unroll
        for (int mi = 0; mi < 2; mi++)
#pragma unroll
            for (int ni = 0; ni < 4; ni++)
#pragma unroll
                for (int q = 0; q < 4; q++) acc[mi][ni][q] = 0.0f;
    } else {
#pragma unroll
        for (int i = 0; i < 8; i++)
#pragma unroll
            for (int j = 0; j < 8; j++) sacc[i][j] = 0.0f;
    }

    load_chunk(0, 0);
    load_chunk(1, 1);

    for (int c = 0; c < NCHUNK; c++) {
        if (c + 1 < NCHUNK) asm volatile("cp.async.wait_group 1;" ::: "memory");
        else                asm volatile("cp.async.wait_group 0;" ::: "memory");
        __syncthreads();     // chunk c visible; all warps done with stage (c+2)%3
        if (c + 2 < NCHUNK) load_chunk(c + 2, (c + 2) % 3);

        const uint32_t* As = (const uint32_t*)(smc + OFF_AS(c % 3));
        const uint32_t* Bs = (const uint32_t*)(smc + OFF_BS(c % 3));

        if (wid < 8) {
            // ---- tensor path: halves 0..111 ----
#pragma unroll
            for (int kk = 0; kk < TK16; kk++) {
                const int kw = kk * 8;
                uint32_t a[2][4], bf[4][2];
#pragma unroll
                for (int mi = 0; mi < 2; mi++) {
                    const uint32_t* ar = As + (warpM * 32 + mi * 16 + g_l) * ASTW + kw + t4;
                    a[mi][0] = ar[0];
                    a[mi][1] = ar[8 * ASTW];
                    a[mi][2] = ar[4];
                    a[mi][3] = ar[8 * ASTW + 4];
                }
#pragma unroll
                for (int ni = 0; ni < 4; ni++) {
                    const uint32_t* br = Bs + (warpN * 32 + ni * 8 + g_l) * ASTW + kw + t4;
                    bf[ni][0] = br[0];
                    bf[ni][1] = br[4];
                }
#pragma unroll
                for (int mi = 0; mi < 2; mi++)
#pragma unroll
                    for (int ni = 0; ni < 4; ni++) mma16(acc[mi][ni], a[mi], bf[ni]);
            }
        } else {
            // ---- SIMT fp32 path: halves 112..127 (words 56..63) ----
            // rows rbase+lr+4i (4-bank spread + broadcast), cols lc+8j (ditto)
            const int rbase = sw * 32;
#pragma unroll
            for (int kp = 0; kp < 8; kp++) {
                const int kw = 56 + kp;
                float2 av[8], bv[8];
#pragma unroll
                for (int i = 0; i < 8; i++) {
                    uint32_t w = As[(rbase + lr + 4 * i) * ASTW + kw];
                    av[i] = __half22float2(*(const __half2*)&w);
                }
#pragma unroll
                for (int j = 0; j < 8; j++) {
                    uint32_t w = Bs[(lc + 8 * j) * ASTW + kw];
                    bv[j] = __half22float2(*(const __half2*)&w);
                }
#pragma unroll
                for (int i = 0; i < 8; i++)
#pragma unroll
                    for (int j = 0; j < 8; j++) {
                        sacc[i][j] = fmaf(av[i].x, bv[j].x, sacc[i][j]);
                        sacc[i][j] = fmaf(av[i].y, bv[j].y, sacc[i][j]);
                    }
            }
        }
    }

    // ---- merge SIMT partials, then fused LSTM cell epilogue ----
    if (wid >= 8) {
        const int rbase = sw * 32;
#pragma unroll
        for (int i = 0; i < 8; i++)
#pragma unroll
            for (int j = 0; j < 8; j++)
                part[(rbase + lr + 4 * i) * 66 + lc + 8 * j] = sacc[i][j];
    }
    __syncthreads();

    if (wid < 8) {
#pragma unroll
        for (int mi = 0; mi < 2; mi++)
#pragma unroll
            for (int rr = 0; rr < 2; rr++)
#pragma unroll
                for (int e = 0; e < 2; e++) {
                    const int q = rr * 2 + e;
                    const int u = 2 * t4 + e;
                    const int m = mBase + warpM * 32 + mi * 16 + rr * 8 + g_l;
                    const int j = j0 + warpN * 8 + u;
                    const int row_l = warpM * 32 + mi * 16 + rr * 8 + g_l;
                    const float* pr = part + row_l * 66 + warpN * 32 + u;
                    const float* bs = biasS + warpN * 32;
                    float ig = sigm(acc[mi][0][q] + pr[0]  + bs[0 * 8 + u]);
                    float fg = sigm(acc[mi][1][q] + pr[8]  + bs[1 * 8 + u]);
                    float gg = tanh_f(acc[mi][2][q] + pr[16] + bs[2 * 8 + u]);
                    float og = sigm(acc[mi][3][q] + pr[24] + bs[3 * 8 + u]);
                    float* cp = g_c + (size_t)m * HD + j;
                    float cv = fg * cp[0] + ig * gg;
                    cp[0] = cv;
                    float h = og * tanh_f(cv);
                    h_out[(size_t)m * HD + j] = __float2half_rn(h);
                }
    }
}

// ===================== prep / init kernels =====================
__global__ void prep_half(const float4* __restrict__ src, __half2* __restrict__ dst, int n4) {
    int i = blockIdx.x * blockDim.x + threadIdx.x;
    if (i < n4) {
        float4 v = src[i];
        dst[2 * i + 0] = __floats2half2_rn(v.x, v.y);
        dst[2 * i + 1] = __floats2half2_rn(v.z, v.w);
    }
}
__global__ void zero_hc_kernel() {
    int idx = blockIdx.x * blockDim.x + threadIdx.x;
    if (idx < NB * HD) { g_h[0][idx] = __float2half(0.0f); g_c[idx] = 0.0f; }
}
__global__ void h2f_kernel(const __half* __restrict__ h, float* __restrict__ f, int n) {
    int i = blockIdx.x * blockDim.x + threadIdx.x;
    if (i < n) f[i] = __half2float(h[i]);
}

// ===================== SIMT head GEMM (exact fp32) =====================
template <int BM, int BN, int BK, int TM, int TN, int MODE>
__global__ __launch_bounds__((BM / TM) * (BN / TN))
void gemm_tn(const float* __restrict__ A, const float* __restrict__ B,
             float* __restrict__ C, int M, int N, int K,
             const float* __restrict__ e0)
{
    constexpr int THREADS = (BM / TM) * (BN / TN);
    static_assert(THREADS == 256, "tiling assumes 256 threads");
    constexpr int KV = BK / 4;
    constexpr int ROWS_PER_IT = THREADS / KV;

    __shared__ float As[BK][BM + 4];
    __shared__ float Bs[BK][BN + 4];

    const int tid = threadIdx.x;
    const int tx  = tid % (BN / TN);
    const int ty  = tid / (BN / TN);
    const int rowBase = blockIdx.y * BM;
    const int colBase = blockIdx.x * BN;
    const int l_r = tid / KV;
    const int l_c = (tid % KV) * 4;

    float acc[TM][TN];
#pragma unroll
    for (int i = 0; i < TM; i++)
#pragma unroll
        for (int j = 0; j < TN; j++) acc[i][j] = 0.0f;

    for (int k0 = 0; k0 < K; k0 += BK) {
#pragma unroll
        for (int r = l_r; r < BM; r += ROWS_PER_IT) {
            float4 v = *reinterpret_cast<const float4*>(
                &A[(size_t)(rowBase + r) * K + k0 + l_c]);
            As[l_c + 0][r] = v.x; As[l_c + 1][r] = v.y;
            As[l_c + 2][r] = v.z; As[l_c + 3][r] = v.w;
        }
#pragma unroll
        for (int r = l_r; r < BN; r += ROWS_PER_IT) {
            float4 v = *reinterpret_cast<const float4*>(
                &B[(size_t)(colBase + r) * K + k0 + l_c]);
            Bs[l_c + 0][r] = v.x; Bs[l_c + 1][r] = v.y;
            Bs[l_c + 2][r] = v.z; Bs[l_c + 3][r] = v.w;
        }
        __syncthreads();
#pragma unroll
        for (int kk = 0; kk < BK; kk++) {
            float ra[TM], rb[TN];
#pragma unroll
            for (int i = 0; i < TM; i++) ra[i] = As[kk][ty * TM + i];
#pragma unroll
            for (int j = 0; j < TN; j++) rb[j] = Bs[kk][tx * TN + j];
#pragma unroll
            for (int i = 0; i < TM; i++)
#pragma unroll
                for (int j = 0; j < TN; j++) acc[i][j] += ra[i] * rb[j];
        }
        __syncthreads();
    }
#pragma unroll
    for (int i = 0; i < TM; i++) {
        const int m = rowBase + ty * TM + i;
#pragma unroll
        for (int j = 0; j < TN; j++) {
            const int n = colBase + tx * TN + j;
            float v = acc[i][j] + e0[n];
            if (MODE == 2) v = fmaxf(v, 0.0f);
            C[(size_t)m * N + n] = v;
        }
    }
}

// ===================== launch =====================
extern "C" void kernel_launch(void* const* d_in, const int* in_sizes, int n_in,
                              void* d_out, int out_size)
{
    const float* x    = (const float*)d_in[0];
    const float* W_ih = (const float*)d_in[1];
    const float* W_hh = (const float*)d_in[2];
    const float* b_ih = (const float*)d_in[3];
    const float* b_hh = (const float*)d_in[4];
    const float* W1   = (const float*)d_in[5];
    const float* b1   = (const float*)d_in[6];
    const float* W2   = (const float*)d_in[7];
    const float* b2   = (const float*)d_in[8];

    float* out = (float*)d_out;          // [256,128]
    float* pre = out + NB * ODIM;        // [256,1024]

    __half *p_h0, *p_h1, *p_whh, *p_wih, *p_x;
    float *p_hf;
    cudaGetSymbolAddress((void**)&p_h0, g_h);
    p_h1 = p_h0 + NB * HD;
    cudaGetSymbolAddress((void**)&p_hf, g_hf);
    cudaGetSymbolAddress((void**)&p_whh, g_whh);
    cudaGetSymbolAddress((void**)&p_wih, g_wih);
    cudaGetSymbolAddress((void**)&p_x, g_x);

    cudaFuncSetAttribute(lstm_step_tc, cudaFuncAttributeMaxDynamicSharedMemorySize, SMEM_DYN);

    zero_hc_kernel<<<(NB * HD + 255) / 256, 256>>>();
    prep_half<<<(G4 * HD / 4 + 255) / 256, 256>>>((const float4*)W_hh, (__half2*)p_whh, G4 * HD / 4);
    prep_half<<<(G4 * DIN / 4 + 255) / 256, 256>>>((const float4*)W_ih, (__half2*)p_wih, G4 * DIN / 4);
    prep_half<<<(NB * TT * DIN / 4 + 255) / 256, 256>>>((const float4*)x, (__half2*)p_x, NB * TT * DIN / 4);

    // recurrence: 128 fused hybrid (tensor + FMA pipe) steps
    for (int t = 0; t < TT; t++) {
        const __half* h_in = (t & 1) ? p_h1 : p_h0;
        __half* h_out      = (t & 1) ? p_h0 : p_h1;
        lstm_step_tc<<<dim3(64, 2), 384, SMEM_DYN>>>(
            h_in, h_out, p_x, p_whh, p_wih, b_ih, b_hh, t);
    }

    // final h (buffer 0 after even step count) -> fp32 for exact head GEMMs
    h2f_kernel<<<(NB * HD + 255) / 256, 256>>>(p_h0, p_hf, NB * HD);

    gemm_tn<64, 128, 16, 4, 8, 2><<<dim3(HD / 128, NB / 64), 256>>>(
        p_hf, W1, pre, NB, HD, HD, b1);
    gemm_tn<64, 128, 16, 4, 8, 3><<<dim3(ODIM / 128, NB / 64), 256>>>(
        pre, W2, out, NB, ODIM, HD, b2);
}